// round 4
// baseline (speedup 1.0000x reference)
#include <cuda_runtime.h>
#include <math.h>

#define NG    2048
#define IMW   128
#define IMH   128
#define NPIX  (IMW*IMH)
#define SEGS  4
#define SEGLEN (NG/SEGS)
#define PPB   64            // pixels per render block
#define EPSV  1e-4f
#define NEARV 0.3f

// Scratch (device globals — no allocation allowed)
__device__ float4 d_pA[NG];   // u, v, ia, ib
__device__ float4 d_pB[NG];   // ic, opa_eff, r, g
__device__ float  d_pC[NG];   // b (color)
__device__ float  d_key[NG];  // depth key
__device__ float4 d_sA[NG];   // sorted copies
__device__ float4 d_sB[NG];
__device__ float  d_sC[NG];

__device__ __forceinline__ float sigmoidf(float x) { return 1.0f / (1.0f + __expf(-x)); }

__global__ void preprocess_kernel(const float* __restrict__ pos,
                                  const float* __restrict__ rgb,
                                  const float* __restrict__ opa,
                                  const float* __restrict__ quat,
                                  const float* __restrict__ scale,
                                  const float* __restrict__ rot,
                                  const float* __restrict__ tran) {
    int i = blockIdx.x * blockDim.x + threadIdx.x;
    if (i >= NG) return;

    // rot (row-major 3x3), tran
    float R00 = rot[0], R01 = rot[1], R02 = rot[2];
    float R10 = rot[3], R11 = rot[4], R12 = rot[5];
    float R20 = rot[6], R21 = rot[7], R22 = rot[8];
    float tx = tran[0], ty = tran[1], tz = tran[2];

    float px = pos[3*i+0], py = pos[3*i+1], pz = pos[3*i+2];
    // pos_cam = pos @ rot.T + tran  (i.e. rot rows dot pos)
    float x = R00*px + R01*py + R02*pz + tx;
    float y = R10*px + R11*py + R12*pz + ty;
    float z = R20*px + R21*py + R22*pz + tz;

    float rn   = sqrtf(x*x + y*y + z*z);
    float invz = 1.0f / z;
    float u = x * invz, v = y * invz;

    // JW rows 0,1 (row 2 of J only feeds the dropped cov2d entries):
    // JW0[k] = (R0k - u*R2k)/z ; JW1[k] = (R1k - v*R2k)/z
    float jw00 = (R00 - u*R20)*invz, jw01 = (R01 - u*R21)*invz, jw02 = (R02 - u*R22)*invz;
    float jw10 = (R10 - v*R20)*invz, jw11 = (R11 - v*R21)*invz, jw12 = (R12 - v*R22)*invz;

    // Quaternion (w,x,y,z) -> rotation matrix (normalized)
    float qw = quat[4*i+0], qx = quat[4*i+1], qy = quat[4*i+2], qz = quat[4*i+3];
    float qn = rsqrtf(qw*qw + qx*qx + qy*qy + qz*qz);
    qw *= qn; qx *= qn; qy *= qn; qz *= qn;
    float M00 = 1.0f - 2.0f*(qy*qy + qz*qz), M01 = 2.0f*(qx*qy - qw*qz), M02 = 2.0f*(qx*qz + qw*qy);
    float M10 = 2.0f*(qx*qy + qw*qz), M11 = 1.0f - 2.0f*(qx*qx + qz*qz), M12 = 2.0f*(qy*qz - qw*qx);
    float M20 = 2.0f*(qx*qz - qw*qy), M21 = 2.0f*(qy*qz + qw*qx), M22 = 1.0f - 2.0f*(qx*qx + qy*qy);

    float s0 = fabsf(scale[3*i+0]) + 1e-4f;
    float s1 = fabsf(scale[3*i+1]) + 1e-4f;
    float s2 = fabsf(scale[3*i+2]) + 1e-4f;

    // w_s[j] = sum_i JW_s[i] * M[i][j] * s[j]  ->  cov2d = w w^T
    float w00 = (jw00*M00 + jw01*M10 + jw02*M20) * s0;
    float w01 = (jw00*M01 + jw01*M11 + jw02*M21) * s1;
    float w02 = (jw00*M02 + jw01*M12 + jw02*M22) * s2;
    float w10 = (jw10*M00 + jw11*M10 + jw12*M20) * s0;
    float w11 = (jw10*M01 + jw11*M11 + jw12*M21) * s1;
    float w12 = (jw10*M02 + jw11*M12 + jw12*M22) * s2;

    float a = w00*w00 + w01*w01 + w02*w02 + EPSV;
    float b = w00*w10 + w01*w11 + w02*w12;
    float c = w10*w10 + w11*w11 + w12*w12 + EPSV;

    float invdet = 1.0f / (a*c - b*b);
    float ia =  c * invdet;
    float ib = -b * invdet;
    float ic =  a * invdet;

    float opa_eff = sigmoidf(opa[i]) * ((z > NEARV) ? 1.0f : 0.0f);
    float cr = sigmoidf(rgb[3*i+0]);
    float cg = sigmoidf(rgb[3*i+1]);
    float cb = sigmoidf(rgb[3*i+2]);

    d_pA[i]  = make_float4(u, v, ia, ib);
    d_pB[i]  = make_float4(ic, opa_eff, cr, cg);
    d_pC[i]  = cb;
    d_key[i] = rn;
}

// Single-block bitonic argsort (ascending by depth), then gather sorted SoA.
__global__ void sort_gather_kernel() {
    __shared__ float sk[NG];
    __shared__ int   si[NG];
    int tid = threadIdx.x;                      // 1024 threads
    for (int i = tid; i < NG; i += 1024) { sk[i] = d_key[i]; si[i] = i; }
    __syncthreads();

    for (int k = 2; k <= NG; k <<= 1) {
        for (int j = k >> 1; j > 0; j >>= 1) {
            for (int i = tid; i < NG; i += 1024) {
                int ixj = i ^ j;
                if (ixj > i) {
                    bool up = ((i & k) == 0);
                    float a = sk[i], b = sk[ixj];
                    if ((a > b) == up) {
                        sk[i] = b; sk[ixj] = a;
                        int t = si[i]; si[i] = si[ixj]; si[ixj] = t;
                    }
                }
            }
            __syncthreads();
        }
    }
    for (int i = tid; i < NG; i += 1024) {
        int o = si[i];
        d_sA[i] = d_pA[o];
        d_sB[i] = d_pB[o];
        d_sC[i] = d_pC[o];
    }
}

// Render: 64 pixels/block x 4 depth-segments/pixel. Each warp owns one segment
// (tid>>6 is warp-uniform) so all lanes read the SAME gaussian record per
// iteration -> broadcast LDG, table stays L1-resident.
__global__ void __launch_bounds__(SEGS*PPB) render_kernel(float* __restrict__ out) {
    int tid = threadIdx.x;
    int pl  = tid & (PPB - 1);       // pixel within block
    int seg = tid >> 6;              // 0..3
    int pix = blockIdx.x * PPB + pl;
    int row = pix >> 7;              // / IMW
    int col = pix & (IMW - 1);
    float pxf = ((float)col - 63.5f) * (1.0f / 128.0f);
    float pyf = ((float)row - 63.5f) * (1.0f / 128.0f);

    float T = 1.0f, cr = 0.0f, cg = 0.0f, cb = 0.0f;
    int beg = seg * SEGLEN, end = beg + SEGLEN;
    #pragma unroll 4
    for (int k = beg; k < end; k++) {
        float4 a  = d_sA[k];
        float4 b  = d_sB[k];
        float  bc = d_sC[k];
        float dx = pxf - a.x;
        float dy = pyf - a.y;
        float power = -0.5f * (a.z*dx*dx + 2.0f*a.w*dx*dy + b.x*dy*dy);
        float al = fminf(b.y * __expf(power), 0.99f);
        float w = T * al;
        cr += w * b.z;
        cg += w * b.w;
        cb += w * bc;
        T *= (1.0f - al);
    }

    __shared__ float4 part[SEGS*PPB];
    part[tid] = make_float4(cr, cg, cb, T);
    __syncthreads();

    if (seg == 0) {
        float4 p0 = part[pl];
        float4 p1 = part[pl + PPB];
        float4 p2 = part[pl + 2*PPB];
        float4 p3 = part[pl + 3*PPB];
        float r = p0.x, g = p0.y, bl = p0.z;
        float Tc = p0.w;
        r += Tc*p1.x; g += Tc*p1.y; bl += Tc*p1.z; Tc *= p1.w;
        r += Tc*p2.x; g += Tc*p2.y; bl += Tc*p2.z; Tc *= p2.w;
        r += Tc*p3.x; g += Tc*p3.y; bl += Tc*p3.z;
        out[pix*3 + 0] = r;
        out[pix*3 + 1] = g;
        out[pix*3 + 2] = bl;
    }
}

extern "C" void kernel_launch(void* const* d_in, const int* in_sizes, int n_in,
                              void* d_out, int out_size) {
    const float* pos   = (const float*)d_in[0];
    const float* rgb   = (const float*)d_in[1];
    const float* opa   = (const float*)d_in[2];
    const float* quat  = (const float*)d_in[3];
    const float* scale = (const float*)d_in[4];
    const float* rot   = (const float*)d_in[5];
    const float* tran  = (const float*)d_in[6];
    float* out = (float*)d_out;

    preprocess_kernel<<<(NG + 255) / 256, 256>>>(pos, rgb, opa, quat, scale, rot, tran);
    sort_gather_kernel<<<1, 1024>>>();
    render_kernel<<<NPIX / PPB, SEGS * PPB>>>(out);
}

// round 8
// speedup vs baseline: 1.8440x; 1.8440x over previous
#include <cuda_runtime.h>
#include <math.h>

#define NG     2048
#define IMW    128
#define IMH    128
#define NPIX   (IMW*IMH)
#define EPSV   1e-4f
#define NEARV  0.3f
#define LOG2E  1.4426950408889634f
#define CUTP   (-26.0f)       // skip when power(log2) < CUTP  (alpha < ~1.5e-8)

// Render config: grid = 256 blocks (128 rows x 2 half-rows of 64 px).
// Block = 512 threads = 16 warps = 16 depth segments (chain NG/16 = 128).
// Warp = 32 lanes = 32 pixel-pairs covering the 64-px span, ONE segment ->
// the cull test is identical across the warp (uniform branch, no divergence).
#define RSEGS   16
#define SEGLEN  (NG/RSEGS)    // 128
#define HALFW   (31.5f/128.0f)

// Scratch (device globals — no allocation allowed)
__device__ float4 d_pA[NG];   // u, v, rmax2, Bc      (unsorted)
__device__ float4 d_pB[NG];   // Ac, Cc, lopa, cr
__device__ float2 d_pC[NG];   // cg, cb
__device__ float4 d_sA[NG];   // sorted copies
__device__ float4 d_sB[NG];
__device__ float2 d_sC[NG];

__device__ __forceinline__ float sigmoidf(float x) { return 1.0f / (1.0f + __expf(-x)); }
__device__ __forceinline__ float ex2f(float x) {
    float y; asm("ex2.approx.ftz.f32 %0, %1;" : "=f"(y) : "f"(x)); return y;
}

__device__ __forceinline__ void preprocess_one(
    int i,
    const float* __restrict__ pos, const float* __restrict__ rgb,
    const float* __restrict__ opa, const float* __restrict__ quat,
    const float* __restrict__ scale,
    float R00,float R01,float R02,float R10,float R11,float R12,
    float R20,float R21,float R22,float tx,float ty,float tz,
    float* __restrict__ key)
{
    float px = pos[3*i+0], py = pos[3*i+1], pz = pos[3*i+2];
    float x = R00*px + R01*py + R02*pz + tx;
    float y = R10*px + R11*py + R12*pz + ty;
    float z = R20*px + R21*py + R22*pz + tz;

    float rn   = sqrtf(x*x + y*y + z*z);
    float invz = 1.0f / z;
    float u = x * invz, v = y * invz;

    // JW rows 0,1 (row 2 feeds only dropped cov2d entries)
    float jw00 = (R00 - u*R20)*invz, jw01 = (R01 - u*R21)*invz, jw02 = (R02 - u*R22)*invz;
    float jw10 = (R10 - v*R20)*invz, jw11 = (R11 - v*R21)*invz, jw12 = (R12 - v*R22)*invz;

    float qw = quat[4*i+0], qx = quat[4*i+1], qy = quat[4*i+2], qz = quat[4*i+3];
    float qn = rsqrtf(qw*qw + qx*qx + qy*qy + qz*qz);
    qw *= qn; qx *= qn; qy *= qn; qz *= qn;
    float M00 = 1.0f - 2.0f*(qy*qy + qz*qz), M01 = 2.0f*(qx*qy - qw*qz), M02 = 2.0f*(qx*qz + qw*qy);
    float M10 = 2.0f*(qx*qy + qw*qz), M11 = 1.0f - 2.0f*(qx*qx + qz*qz), M12 = 2.0f*(qy*qz - qw*qx);
    float M20 = 2.0f*(qx*qz - qw*qy), M21 = 2.0f*(qy*qz + qw*qx), M22 = 1.0f - 2.0f*(qx*qx + qy*qy);

    float s0 = fabsf(scale[3*i+0]) + 1e-4f;
    float s1 = fabsf(scale[3*i+1]) + 1e-4f;
    float s2 = fabsf(scale[3*i+2]) + 1e-4f;

    float w00 = (jw00*M00 + jw01*M10 + jw02*M20) * s0;
    float w01 = (jw00*M01 + jw01*M11 + jw02*M21) * s1;
    float w02 = (jw00*M02 + jw01*M12 + jw02*M22) * s2;
    float w10 = (jw10*M00 + jw11*M10 + jw12*M20) * s0;
    float w11 = (jw10*M01 + jw11*M11 + jw12*M21) * s1;
    float w12 = (jw10*M02 + jw11*M12 + jw12*M22) * s2;

    float a = w00*w00 + w01*w01 + w02*w02 + EPSV;
    float b = w00*w10 + w01*w11 + w02*w12;
    float c = w10*w10 + w11*w11 + w12*w12 + EPSV;

    float invdet = 1.0f / (a*c - b*b);
    float ia =  c * invdet;   // conic
    float ib = -b * invdet;
    float ic =  a * invdet;

    // power (base-2) = Ac*dx^2 + Bc*dx*dy + Cc*dy^2 + lopa
    float Ac = -0.5f * LOG2E * ia;
    float Bc = -LOG2E * ib;
    float Cc = -0.5f * LOG2E * ic;
    float opa_eff = sigmoidf(opa[i]) * ((z > NEARV) ? 1.0f : 0.0f);
    float lopa = log2f(opa_eff);          // -inf when culled

    // Largest (closest to 0) eigenvalue of [[Ac,Bc/2],[Bc/2,Cc]] (neg def):
    // power <= lam*|d|^2 + lopa  ->  safe skip when |d|^2_min > rmax2.
    float mh  = 0.5f * (Ac + Cc);
    float dh  = 0.5f * (Ac - Cc);
    float lam = mh + sqrtf(dh*dh + 0.25f*Bc*Bc);      // < 0
    float rmax2 = (CUTP - lopa) / lam;                 // -inf when lopa=-inf

    float cr = sigmoidf(rgb[3*i+0]);
    float cg = sigmoidf(rgb[3*i+1]);
    float cb = sigmoidf(rgb[3*i+2]);

    d_pA[i] = make_float4(u, v, rmax2, Bc);
    d_pB[i] = make_float4(Ac, Cc, lopa, cr);
    d_pC[i] = make_float2(cg, cb);
    key[i]  = rn;
}

// Fused: preprocess + bitonic argsort by depth + gather sorted SoA. One block.
__global__ void __launch_bounds__(1024) prep_sort_kernel(
    const float* __restrict__ pos, const float* __restrict__ rgb,
    const float* __restrict__ opa, const float* __restrict__ quat,
    const float* __restrict__ scale, const float* __restrict__ rot,
    const float* __restrict__ tran)
{
    __shared__ float sk[NG];
    __shared__ int   si[NG];
    int tid = threadIdx.x;

    float R00 = rot[0], R01 = rot[1], R02 = rot[2];
    float R10 = rot[3], R11 = rot[4], R12 = rot[5];
    float R20 = rot[6], R21 = rot[7], R22 = rot[8];
    float tx = tran[0], ty = tran[1], tz = tran[2];

    #pragma unroll
    for (int i = tid; i < NG; i += 1024) {
        preprocess_one(i, pos, rgb, opa, quat, scale,
                       R00,R01,R02,R10,R11,R12,R20,R21,R22,tx,ty,tz, sk);
        si[i] = i;
    }
    __syncthreads();

    for (int k = 2; k <= NG; k <<= 1) {
        for (int j = k >> 1; j > 0; j >>= 1) {
            #pragma unroll
            for (int i = tid; i < NG; i += 1024) {
                int ixj = i ^ j;
                if (ixj > i) {
                    bool up = ((i & k) == 0);
                    float a = sk[i], b = sk[ixj];
                    if ((a > b) == up) {
                        sk[i] = b; sk[ixj] = a;
                        int t = si[i]; si[i] = si[ixj]; si[ixj] = t;
                    }
                }
            }
            __syncthreads();
        }
    }
    #pragma unroll
    for (int i = tid; i < NG; i += 1024) {
        int o = si[i];
        d_sA[i] = d_pA[o];
        d_sB[i] = d_pB[o];
        d_sC[i] = d_pC[o];
    }
}

__global__ void __launch_bounds__(RSEGS*32) render_kernel(float* __restrict__ out) {
    int tid  = threadIdx.x;
    int lane = tid & 31;          // pixel-pair within the 64-px span
    int seg  = tid >> 5;          // 0..15 depth segment
    int half = blockIdx.x & 1;
    int row  = blockIdx.x >> 1;
    int col0 = half*64 + lane*2;

    float pyf = ((float)row  - 63.5f) * (1.0f/128.0f);
    float px0 = ((float)col0 - 63.5f) * (1.0f/128.0f);
    float px1 = px0 + (1.0f/128.0f);
    float xc  = ((float)(half*64) - 32.0f) * (1.0f/128.0f);  // span center

    float T0 = 1.0f, T1 = 1.0f;
    float r0 = 0.f, g0 = 0.f, b0 = 0.f;
    float r1 = 0.f, g1 = 0.f, b1 = 0.f;

    float dy  = 0.f;  // set per gaussian
    int beg = seg * SEGLEN;
    for (int k = beg; k < beg + SEGLEN; k++) {
        float4 A = d_sA[k];                // u, v, rmax2, Bc
        dy = pyf - A.y;
        float du  = fabsf(xc - A.x);
        float dxm = fmaxf(du - HALFW, 0.0f);
        // warp-uniform conservative reject (all lanes agree)
        if (__fmaf_rn(dy, dy, dxm*dxm) <= A.z) {
            float4 B = d_sB[k];            // Ac, Cc, lopa, cr
            float2 C = d_sC[k];            // cg, cb
            float bdy = A.w * dy;                          // Bc*dy
            float cdy = __fmaf_rn(B.y, dy*dy, B.z);        // Cc*dy^2 + lopa
            float dx0 = px0 - A.x;
            float dx1 = px1 - A.x;
            float a0  = __fmaf_rn(dx0, __fmaf_rn(B.x, dx0, bdy), cdy);
            float a1  = __fmaf_rn(dx1, __fmaf_rn(B.x, dx1, bdy), cdy);
            float al0 = fminf(ex2f(a0), 0.99f);
            float al1 = fminf(ex2f(a1), 0.99f);
            float w0 = T0 * al0, w1 = T1 * al1;
            r0 = __fmaf_rn(w0, B.w, r0);  r1 = __fmaf_rn(w1, B.w, r1);
            g0 = __fmaf_rn(w0, C.x, g0);  g1 = __fmaf_rn(w1, C.x, g1);
            b0 = __fmaf_rn(w0, C.y, b0);  b1 = __fmaf_rn(w1, C.y, b1);
            T0 = __fmaf_rn(-al0, T0, T0);
            T1 = __fmaf_rn(-al1, T1, T1);
        }
    }

    __shared__ float4 part[RSEGS][64];
    part[seg][lane*2 + 0] = make_float4(r0, g0, b0, T0);
    part[seg][lane*2 + 1] = make_float4(r1, g1, b1, T1);
    __syncthreads();

    // Threads 0..63 combine the 16 depth segments front-to-back.
    if (tid < 64) {
        float4 p0 = part[0][tid];
        float r = p0.x, g = p0.y, b = p0.z, T = p0.w;
        #pragma unroll
        for (int s = 1; s < RSEGS; s++) {
            float4 p = part[s][tid];
            r = __fmaf_rn(T, p.x, r);
            g = __fmaf_rn(T, p.y, g);
            b = __fmaf_rn(T, p.z, b);
            T *= p.w;
        }
        int pix = row * IMW + half*64 + tid;
        out[pix*3 + 0] = r;
        out[pix*3 + 1] = g;
        out[pix*3 + 2] = b;
    }
}

extern "C" void kernel_launch(void* const* d_in, const int* in_sizes, int n_in,
                              void* d_out, int out_size) {
    const float* pos   = (const float*)d_in[0];
    const float* rgb   = (const float*)d_in[1];
    const float* opa   = (const float*)d_in[2];
    const float* quat  = (const float*)d_in[3];
    const float* scale = (const float*)d_in[4];
    const float* rot   = (const float*)d_in[5];
    const float* tran  = (const float*)d_in[6];
    float* out = (float*)d_out;

    prep_sort_kernel<<<1, 1024>>>(pos, rgb, opa, quat, scale, rot, tran);
    render_kernel<<<IMH*2, RSEGS*32>>>(out);
}

// round 10
// speedup vs baseline: 2.5518x; 1.3839x over previous
#include <cuda_runtime.h>
#include <math.h>

#define NG     2048
#define IMW    128
#define IMH    128
#define NPIX   (IMW*IMH)
#define EPSV   1e-4f
#define NEARV  0.3f
#define LOG2E  1.4426950408889634f
#define CUTP   (-26.0f)     // skip when power(log2) < CUTP (alpha < ~1.5e-8)

// Render: 4 depth groups x (128 rows x 2 half-rows) = 1024 blocks.
// Block = 256 threads = 8 warps = 8 segments (chain 64) within its group.
// Warp = 32 lanes = 32 pixel-pairs spanning 64 px -> cull test warp-uniform.
#define RGROUPS 4
#define RSEGS_B 8
#define CHAIN   (NG/(RGROUPS*RSEGS_B))   // 64
#define HALFW   (31.5f/128.0f)

// Scratch (device globals — no allocation allowed)
__device__ float4 d_pA[NG];       // u, v, rmax2, Bc   (unsorted)
__device__ float4 d_pB[NG];       // Ac, Cc, lopa, cr
__device__ float2 d_pC[NG];       // cg, cb
__device__ float  d_key[NG];
__device__ float4 d_sA[NG + 1];   // sorted (+1 pad for prefetch)
__device__ float4 d_sB[NG];
__device__ float2 d_sC[NG];
__device__ float4 d_part[RGROUPS][NPIX];   // per-group partials (r,g,b,T)

__device__ __forceinline__ float sigmoidf(float x) { return 1.0f / (1.0f + __expf(-x)); }
__device__ __forceinline__ float ex2f(float x) {
    float y; asm("ex2.approx.ftz.f32 %0, %1;" : "=f"(y) : "f"(x)); return y;
}

__global__ void __launch_bounds__(128) preprocess_kernel(
    const float* __restrict__ pos, const float* __restrict__ rgb,
    const float* __restrict__ opa, const float* __restrict__ quat,
    const float* __restrict__ scale, const float* __restrict__ rot,
    const float* __restrict__ tran)
{
    int i = blockIdx.x * blockDim.x + threadIdx.x;
    if (i >= NG) return;

    float R00 = rot[0], R01 = rot[1], R02 = rot[2];
    float R10 = rot[3], R11 = rot[4], R12 = rot[5];
    float R20 = rot[6], R21 = rot[7], R22 = rot[8];
    float tx = tran[0], ty = tran[1], tz = tran[2];

    float px = pos[3*i+0], py = pos[3*i+1], pz = pos[3*i+2];
    float x = R00*px + R01*py + R02*pz + tx;
    float y = R10*px + R11*py + R12*pz + ty;
    float z = R20*px + R21*py + R22*pz + tz;

    float rn   = sqrtf(x*x + y*y + z*z);
    float invz = 1.0f / z;
    float u = x * invz, v = y * invz;

    float jw00 = (R00 - u*R20)*invz, jw01 = (R01 - u*R21)*invz, jw02 = (R02 - u*R22)*invz;
    float jw10 = (R10 - v*R20)*invz, jw11 = (R11 - v*R21)*invz, jw12 = (R12 - v*R22)*invz;

    float qw = quat[4*i+0], qx = quat[4*i+1], qy = quat[4*i+2], qz = quat[4*i+3];
    float qn = rsqrtf(qw*qw + qx*qx + qy*qy + qz*qz);
    qw *= qn; qx *= qn; qy *= qn; qz *= qn;
    float M00 = 1.0f - 2.0f*(qy*qy + qz*qz), M01 = 2.0f*(qx*qy - qw*qz), M02 = 2.0f*(qx*qz + qw*qy);
    float M10 = 2.0f*(qx*qy + qw*qz), M11 = 1.0f - 2.0f*(qx*qx + qz*qz), M12 = 2.0f*(qy*qz - qw*qx);
    float M20 = 2.0f*(qx*qz - qw*qy), M21 = 2.0f*(qy*qz + qw*qx), M22 = 1.0f - 2.0f*(qx*qx + qy*qy);

    float s0 = fabsf(scale[3*i+0]) + 1e-4f;
    float s1 = fabsf(scale[3*i+1]) + 1e-4f;
    float s2 = fabsf(scale[3*i+2]) + 1e-4f;

    float w00 = (jw00*M00 + jw01*M10 + jw02*M20) * s0;
    float w01 = (jw00*M01 + jw01*M11 + jw02*M21) * s1;
    float w02 = (jw00*M02 + jw01*M12 + jw02*M22) * s2;
    float w10 = (jw10*M00 + jw11*M10 + jw12*M20) * s0;
    float w11 = (jw10*M01 + jw11*M11 + jw12*M21) * s1;
    float w12 = (jw10*M02 + jw11*M12 + jw12*M22) * s2;

    float a = w00*w00 + w01*w01 + w02*w02 + EPSV;
    float b = w00*w10 + w01*w11 + w02*w12;
    float c = w10*w10 + w11*w11 + w12*w12 + EPSV;

    float invdet = 1.0f / (a*c - b*b);
    float ia =  c * invdet;
    float ib = -b * invdet;
    float ic =  a * invdet;

    // power(log2) = Ac*dx^2 + Bc*dx*dy + Cc*dy^2 + lopa
    float Ac = -0.5f * LOG2E * ia;
    float Bc = -LOG2E * ib;
    float Cc = -0.5f * LOG2E * ic;
    float opa_eff = sigmoidf(opa[i]) * ((z > NEARV) ? 1.0f : 0.0f);
    float lopa = log2f(opa_eff);               // -inf when near-culled

    // Least-negative eigenvalue of the conic quadratic -> safe skip radius.
    float mh  = 0.5f * (Ac + Cc);
    float dh  = 0.5f * (Ac - Cc);
    float lam = mh + sqrtf(dh*dh + 0.25f*Bc*Bc);   // < 0
    float rmax2 = (CUTP - lopa) / lam;             // -inf when lopa=-inf

    float cr = sigmoidf(rgb[3*i+0]);
    float cg = sigmoidf(rgb[3*i+1]);
    float cb = sigmoidf(rgb[3*i+2]);

    d_pA[i] = make_float4(u, v, rmax2, Bc);
    d_pB[i] = make_float4(Ac, Cc, lopa, cr);
    d_pC[i] = make_float2(cg, cb);
    d_key[i] = rn;
}

// Counting-rank sort (stable, == jnp.argsort order) + scatter. 16 blocks.
// Block handles 128 gaussians; 1024 threads = 128 gaussians x 8 key-chunks.
// Thread map: c = tid>>7 (chunk), gl = tid&127 -> warp lanes share chunk ->
// all lanes read the same smem key word (broadcast, conflict-free).
__global__ void __launch_bounds__(1024) rank_scatter_kernel() {
    __shared__ float sk[NG];
    __shared__ int scnt[128][9];      // pad to 9 ints: no bank conflicts
    int tid = threadIdx.x;
    for (int i = tid; i < NG; i += 1024) sk[i] = d_key[i];
    __syncthreads();

    int c  = tid >> 7;                // 0..7
    int gl = tid & 127;               // 0..127
    int gi = blockIdx.x * 128 + gl;
    float myk = sk[gi];

    int cnt = 0;
    int j0 = c * (NG/8);
    #pragma unroll 8
    for (int j = j0; j < j0 + NG/8; j++) {
        float kj = sk[j];
        cnt += (kj < myk) || (kj == myk && j < gi);
    }
    scnt[gl][c] = cnt;
    __syncthreads();

    if (c == 0) {
        int rank = 0;
        #pragma unroll
        for (int q = 0; q < 8; q++) rank += scnt[gl][q];
        d_sA[rank] = d_pA[gi];
        d_sB[rank] = d_pB[gi];
        d_sC[rank] = d_pC[gi];
    }
}

__global__ void __launch_bounds__(RSEGS_B*32) render_kernel() {
    int tid  = threadIdx.x;
    int lane = tid & 31;               // pixel-pair in 64-px span
    int seg  = tid >> 5;               // 0..7 segment within group
    int idx  = blockIdx.x;
    int grp  = idx & (RGROUPS-1);
    int half = (idx >> 2) & 1;
    int row  = idx >> 3;
    int col0 = half*64 + lane*2;

    float pyf = ((float)row  - 63.5f) * (1.0f/128.0f);
    float px0 = ((float)col0 - 63.5f) * (1.0f/128.0f);
    float px1 = px0 + (1.0f/128.0f);
    float xc  = ((float)(half*64) - 32.0f) * (1.0f/128.0f);

    float T0 = 1.0f, T1 = 1.0f;
    float r0 = 0.f, g0 = 0.f, b0 = 0.f;
    float r1 = 0.f, g1 = 0.f, b1 = 0.f;

    int beg = grp * (NG/RGROUPS) + seg * CHAIN;
    float4 A = d_sA[beg];              // prefetched cull record
    for (int k = beg; k < beg + CHAIN; k++) {
        float4 An = d_sA[k + 1];       // prefetch next (pad slot at NG)
        float dy  = pyf - A.y;
        float du  = fabsf(xc - A.x);
        float dxm = fmaxf(du - HALFW, 0.0f);
        if (__fmaf_rn(dy, dy, dxm*dxm) <= A.z) {     // warp-uniform
            float4 B = d_sB[k];        // Ac, Cc, lopa, cr
            float2 C = d_sC[k];        // cg, cb
            float bdy = A.w * dy;
            float cdy = __fmaf_rn(B.y, dy*dy, B.z);
            float dx0 = px0 - A.x;
            float dx1 = px1 - A.x;
            float a0  = __fmaf_rn(dx0, __fmaf_rn(B.x, dx0, bdy), cdy);
            float a1  = __fmaf_rn(dx1, __fmaf_rn(B.x, dx1, bdy), cdy);
            float al0 = fminf(ex2f(a0), 0.99f);
            float al1 = fminf(ex2f(a1), 0.99f);
            float w0 = T0 * al0, w1 = T1 * al1;
            r0 = __fmaf_rn(w0, B.w, r0);  r1 = __fmaf_rn(w1, B.w, r1);
            g0 = __fmaf_rn(w0, C.x, g0);  g1 = __fmaf_rn(w1, C.x, g1);
            b0 = __fmaf_rn(w0, C.y, b0);  b1 = __fmaf_rn(w1, C.y, b1);
            T0 = __fmaf_rn(-al0, T0, T0);
            T1 = __fmaf_rn(-al1, T1, T1);
        }
        A = An;
    }

    __shared__ float4 part[RSEGS_B][64];
    part[seg][lane*2 + 0] = make_float4(r0, g0, b0, T0);
    part[seg][lane*2 + 1] = make_float4(r1, g1, b1, T1);
    __syncthreads();

    if (tid < 64) {
        float4 p0 = part[0][tid];
        float r = p0.x, g = p0.y, b = p0.z, T = p0.w;
        #pragma unroll
        for (int s = 1; s < RSEGS_B; s++) {
            float4 p = part[s][tid];
            r = __fmaf_rn(T, p.x, r);
            g = __fmaf_rn(T, p.y, g);
            b = __fmaf_rn(T, p.z, b);
            T *= p.w;
        }
        d_part[grp][row*IMW + half*64 + tid] = make_float4(r, g, b, T);
    }
}

__global__ void __launch_bounds__(256) combine_kernel(float* __restrict__ out) {
    int p = blockIdx.x * blockDim.x + threadIdx.x;   // 0..NPIX-1
    float4 a = d_part[0][p];
    float r = a.x, g = a.y, b = a.z, T = a.w;
    #pragma unroll
    for (int s = 1; s < RGROUPS; s++) {
        float4 q = d_part[s][p];
        r = __fmaf_rn(T, q.x, r);
        g = __fmaf_rn(T, q.y, g);
        b = __fmaf_rn(T, q.z, b);
        T *= q.w;
    }
    out[p*3 + 0] = r;
    out[p*3 + 1] = g;
    out[p*3 + 2] = b;
}

extern "C" void kernel_launch(void* const* d_in, const int* in_sizes, int n_in,
                              void* d_out, int out_size) {
    const float* pos   = (const float*)d_in[0];
    const float* rgb   = (const float*)d_in[1];
    const float* opa   = (const float*)d_in[2];
    const float* quat  = (const float*)d_in[3];
    const float* scale = (const float*)d_in[4];
    const float* rot   = (const float*)d_in[5];
    const float* tran  = (const float*)d_in[6];
    float* out = (float*)d_out;

    preprocess_kernel<<<NG/128, 128>>>(pos, rgb, opa, quat, scale, rot, tran);
    rank_scatter_kernel<<<NG/128, 1024>>>();
    render_kernel<<<IMH*2*RGROUPS, RSEGS_B*32>>>();
    combine_kernel<<<NPIX/256, 256>>>(out);
}